// round 6
// baseline (speedup 1.0000x reference)
#include <cuda_runtime.h>
#include <cuda_bf16.h>
#include <cstdint>
#include <math.h>

#define INST   64
#define NVOCAB 128
#define ED     256
#define HID    1024
#define BATCH  2048

// Precomputed HL[i] = E_l[i] @ W1[i], HR[i] = E_r[i] @ W1[i]  (fp32 scratch)
__device__ float g_HL[INST * NVOCAB * HID];
__device__ float g_HR[INST * NVOCAB * HID];
// W2 preconverted to tf32 bit patterns, layout [inst][k][n]
__device__ uint32_t g_W2t[INST * HID * NVOCAB];

__device__ __forceinline__ uint32_t f2tf(float f) {
    uint32_t u;
    asm("cvt.rna.tf32.f32 %0, %1;" : "=r"(u) : "f"(f));
    return u;
}
__device__ __forceinline__ void mma8(float* c, const uint32_t* a, const uint32_t* b) {
    asm volatile(
        "mma.sync.aligned.m16n8k8.row.col.f32.tf32.tf32.f32 "
        "{%0,%1,%2,%3}, {%4,%5,%6,%7}, {%8,%9}, {%0,%1,%2,%3};"
        : "+f"(c[0]), "+f"(c[1]), "+f"(c[2]), "+f"(c[3])
        : "r"(a[0]), "r"(a[1]), "r"(a[2]), "r"(a[3]), "r"(b[0]), "r"(b[1]));
}
__device__ __forceinline__ float gelu_exact(float x) {
    return 0.5f * x * (1.0f + erff(x * 0.7071067811865476f));
}
__device__ __forceinline__ uint32_t smem_u32(const void* p) {
    uint32_t a;
    asm("{ .reg .u64 t; cvta.to.shared.u64 t, %1; cvt.u32.u64 %0, t; }" : "=r"(a) : "l"(p));
    return a;
}

// Shared tile strides (words). Conflict-free fragment loads:
//   A bank = (4*row + k) % 32, B bank = (8*k + n) % 32
#define ASTR 36
#define BSTR 136
#define ASZW (128 * ASTR)     // 4608 words
#define BSZW (32 * BSTR)      // 4352 words
#define NKT  (HID / 32)       // 32 k-tiles in phase 2
#define NKT1 (ED / 32)        // 8 k-tiles in phase 1
#define NSTG 3                // B pipeline depth
#define GEMM_SMEM ((ASZW + NSTG * BSZW) * 4)   // 70656 B -> 2 CTAs/SM

// 4-warp CTA, warp tile 64x64: s=4 m16-tiles, q=8 n8-tiles, 32 MMA/slice.
// wm = (w&1)*64, wn = (w>>1)*64.
#define COMPUTE_TILE64(Ap, Bp)                                                  \
    _Pragma("unroll")                                                           \
    for (int ks = 0; ks < 4; ks++) {                                            \
        const int kk = ks * 8;                                                  \
        uint32_t af[4][4];                                                      \
        _Pragma("unroll")                                                       \
        for (int s = 0; s < 4; s++) {                                           \
            int r0 = wm + s * 16 + g;                                           \
            af[s][0] = (Ap)[r0 * ASTR + kk + tg];                               \
            af[s][1] = (Ap)[(r0 + 8) * ASTR + kk + tg];                         \
            af[s][2] = (Ap)[r0 * ASTR + kk + 4 + tg];                           \
            af[s][3] = (Ap)[(r0 + 8) * ASTR + kk + 4 + tg];                     \
        }                                                                       \
        uint32_t bf[8][2];                                                      \
        _Pragma("unroll")                                                       \
        for (int q = 0; q < 8; q++) {                                           \
            int nb = wn + q * 8 + g;                                            \
            bf[q][0] = (Bp)[(kk + tg) * BSTR + nb];                             \
            bf[q][1] = (Bp)[(kk + 4 + tg) * BSTR + nb];                         \
        }                                                                       \
        _Pragma("unroll")                                                       \
        for (int s = 0; s < 4; s++)                                             \
            _Pragma("unroll")                                                   \
            for (int q = 0; q < 8; q++)                                         \
                mma8(c[s][q], af[s], bf[q]);                                    \
    }

// ---------------------------------------------------------------------------
// Phase 0: W2 fp32 -> tf32 bit patterns (one-time, ~11us)
// ---------------------------------------------------------------------------
__global__ __launch_bounds__(256) void w2t_kernel(const float* __restrict__ W2)
{
    size_t idx = ((size_t)blockIdx.x * 256 + threadIdx.x) * 4;
    float4 v = *reinterpret_cast<const float4*>(W2 + idx);
    *reinterpret_cast<uint4*>(g_W2t + idx) =
        make_uint4(f2tf(v.x), f2tf(v.y), f2tf(v.z), f2tf(v.w));
}

// ---------------------------------------------------------------------------
// Phase 1: HL/HR[i] = E[i] (128x256) @ W1[i] (256x1024)
// 4-warp 64x64 tiles, cp.async B (depth 3). grid (8, 64, 2), 128 threads.
// ---------------------------------------------------------------------------
__global__ __launch_bounds__(128) void phase1_kernel(
    const float* __restrict__ El, const float* __restrict__ Er,
    const float* __restrict__ W1)
{
    extern __shared__ uint32_t dsm[];
    uint32_t* A_s = dsm;
    uint32_t* Bs  = dsm + ASZW;
    const uint32_t bs_base = smem_u32(Bs);

    const int nt = blockIdx.x, inst = blockIdx.y, side = blockIdx.z;
    const float* E   = (side ? Er : El) + inst * NVOCAB * ED;
    float*       Hst = (side ? g_HR : g_HL) + inst * NVOCAB * HID + nt * 128;
    const float* W   = W1 + inst * ED * HID + nt * 128;

    const int t    = threadIdx.x;
    const int lane = t & 31, w = t >> 5;
    const int wm = (w & 1) * 64, wn = (w >> 1) * 64;
    const int g = lane >> 2, tg = lane & 3;
    // A-producer mapping: 4 lanes/row, row = (t>>2)+32j, col group c8=(t&3)*8
    const int r0a = t >> 2, c8 = (t & 3) * 8;

    float c[4][8][4];
#pragma unroll
    for (int s = 0; s < 4; s++)
#pragma unroll
        for (int q = 0; q < 8; q++)
#pragma unroll
            for (int v = 0; v < 4; v++) c[s][q][v] = 0.f;

#define PREFETCH_B1(KT) do {                                                    \
        if ((KT) < NKT1) {                                                      \
            const uint32_t bb = bs_base + (uint32_t)((((KT) % NSTG)) * (BSZW * 4)); \
            const float* srcb = W + (size_t)(KT) * 32 * HID;                    \
            _Pragma("unroll")                                                   \
            for (int j = 0; j < 8; j++) {                                       \
                int cc = t + 128 * j;                                           \
                int k = cc >> 5, nc = (cc & 31) * 4;                            \
                uint32_t dst = bb + (uint32_t)(k * BSTR + nc) * 4;              \
                const float* src = srcb + (size_t)k * HID + nc;                 \
                asm volatile("cp.async.cg.shared.global [%0], [%1], 16;"        \
                             :: "r"(dst), "l"(src) : "memory");                 \
            }                                                                   \
        }                                                                       \
        asm volatile("cp.async.commit_group;" ::: "memory");                    \
    } while (0)

    PREFETCH_B1(0); PREFETCH_B1(1); PREFETCH_B1(2);

#pragma unroll 1
    for (int kt = 0; kt < NKT1; kt++) {
        const int k0 = kt * 32;
        // Produce A tile: tf32 convert of E rows
#pragma unroll
        for (int j = 0; j < 4; j++) {
            int row = r0a + 32 * j;
            float4 v0 = *reinterpret_cast<const float4*>(E + row * ED + k0 + c8);
            float4 v1 = *reinterpret_cast<const float4*>(E + row * ED + k0 + c8 + 4);
            *reinterpret_cast<uint4*>(&A_s[row * ASTR + c8]) =
                make_uint4(f2tf(v0.x), f2tf(v0.y), f2tf(v0.z), f2tf(v0.w));
            *reinterpret_cast<uint4*>(&A_s[row * ASTR + c8 + 4]) =
                make_uint4(f2tf(v1.x), f2tf(v1.y), f2tf(v1.z), f2tf(v1.w));
        }
        asm volatile("cp.async.wait_group %0;" :: "n"(NSTG - 1) : "memory");
        __syncthreads();

        // Convert B tile fp32 -> tf32 in smem (bit-identical to w2t path)
        uint32_t* Bp = Bs + (kt % NSTG) * BSZW;
#pragma unroll
        for (int j = 0; j < 8; j++) {
            int cc = t + 128 * j;
            int k = cc >> 5, nc = (cc & 31) * 4;
            uint4* p = reinterpret_cast<uint4*>(&Bp[k * BSTR + nc]);
            uint4 u = *p;
            u.x = f2tf(__uint_as_float(u.x));
            u.y = f2tf(__uint_as_float(u.y));
            u.z = f2tf(__uint_as_float(u.z));
            u.w = f2tf(__uint_as_float(u.w));
            *p = u;
        }
        __syncthreads();
        COMPUTE_TILE64(A_s, Bp);
        __syncthreads();
        PREFETCH_B1(kt + NSTG);
    }

#pragma unroll
    for (int s = 0; s < 4; s++) {
        int row = wm + s * 16 + g;
#pragma unroll
        for (int q = 0; q < 8; q++) {
            int col = wn + q * 8 + 2 * tg;
            *reinterpret_cast<float2*>(Hst + row * HID + col) =
                make_float2(c[s][q][0], c[s][q][1]);
            *reinterpret_cast<float2*>(Hst + (row + 8) * HID + col) =
                make_float2(c[s][q][2], c[s][q][3]);
        }
    }
}

// ---------------------------------------------------------------------------
// Phase 2: out[b,i,:] = gelu(HL[i,a1[b],:] + HR[i,a2[b],:]) @ W2[i]
// 4-warp 64x64 tiles, fused gather+gelu A, cp.async B depth 3.
// grid (16 m-tiles, 64 instances), 128 threads.
// ---------------------------------------------------------------------------
__global__ __launch_bounds__(128) void phase2_kernel(
    const int* __restrict__ a, float* __restrict__ out)
{
    extern __shared__ uint32_t dsm[];
    uint32_t* A_s = dsm;
    uint32_t* Bs  = dsm + ASZW;
    const uint32_t bs_base = smem_u32(Bs);

    const int mt = blockIdx.x, inst = blockIdx.y;
    const uint32_t* Wt = g_W2t + (size_t)inst * HID * NVOCAB;

    const int t    = threadIdx.x;
    const int lane = t & 31, w = t >> 5;
    const int wm = (w & 1) * 64, wn = (w >> 1) * 64;
    const int g = lane >> 2, tg = lane & 3;
    const int r0a = t >> 2, c8 = (t & 3) * 8;

    // Hoist gather offsets (u32 byte offsets into g_HL/g_HR)
    uint32_t offL[4], offR[4];
#pragma unroll
    for (int j = 0; j < 4; j++) {
        int row = r0a + 32 * j;
        int b = mt * 128 + row;
        int i1 = a[2 * b], i2 = a[2 * b + 1];
        offL[j] = (uint32_t)(inst * NVOCAB + i1) * (HID * 4);
        offR[j] = (uint32_t)(inst * NVOCAB + i2) * (HID * 4);
    }
    const char* baseL = (const char*)g_HL;
    const char* baseR = (const char*)g_HR;

    float c[4][8][4];
#pragma unroll
    for (int s = 0; s < 4; s++)
#pragma unroll
        for (int q = 0; q < 8; q++)
#pragma unroll
            for (int v = 0; v < 4; v++) c[s][q][v] = 0.f;

#define PREFETCH_B2(KT) do {                                                    \
        if ((KT) < NKT) {                                                       \
            const uint32_t bb = bs_base + (uint32_t)((((KT) % NSTG)) * (BSZW * 4)); \
            const uint32_t* srcb = Wt + (size_t)(KT) * 32 * NVOCAB;             \
            _Pragma("unroll")                                                   \
            for (int j = 0; j < 8; j++) {                                       \
                int cc = t + 128 * j;                                           \
                int k = cc >> 5, nc = (cc & 31) * 4;                            \
                uint32_t dst = bb + (uint32_t)(k * BSTR + nc) * 4;              \
                const uint32_t* src = srcb + k * NVOCAB + nc;                   \
                asm volatile("cp.async.cg.shared.global [%0], [%1], 16;"        \
                             :: "r"(dst), "l"(src) : "memory");                 \
            }                                                                   \
        }                                                                       \
        asm volatile("cp.async.commit_group;" ::: "memory");                    \
    } while (0)

    PREFETCH_B2(0); PREFETCH_B2(1); PREFETCH_B2(2);

#pragma unroll 1
    for (int kt = 0; kt < NKT; kt++) {
        const uint32_t kb = (uint32_t)(kt * 32 + c8) * 4;   // byte offset in row
        // Produce A tile: gather + add + exact gelu + tf32
#pragma unroll
        for (int j = 0; j < 4; j++) {
            int row = r0a + 32 * j;
            float4 l0 = *reinterpret_cast<const float4*>(baseL + offL[j] + kb);
            float4 l1 = *reinterpret_cast<const float4*>(baseL + offL[j] + kb + 16);
            float4 q0 = *reinterpret_cast<const float4*>(baseR + offR[j] + kb);
            float4 q1 = *reinterpret_cast<const float4*>(baseR + offR[j] + kb + 16);
            uint4 u0, u1;
            u0.x = f2tf(gelu_exact(l0.x + q0.x));
            u0.y = f2tf(gelu_exact(l0.y + q0.y));
            u0.z = f2tf(gelu_exact(l0.z + q0.z));
            u0.w = f2tf(gelu_exact(l0.w + q0.w));
            u1.x = f2tf(gelu_exact(l1.x + q1.x));
            u1.y = f2tf(gelu_exact(l1.y + q1.y));
            u1.z = f2tf(gelu_exact(l1.z + q1.z));
            u1.w = f2tf(gelu_exact(l1.w + q1.w));
            *reinterpret_cast<uint4*>(&A_s[row * ASTR + c8]) = u0;
            *reinterpret_cast<uint4*>(&A_s[row * ASTR + c8 + 4]) = u1;
        }

        asm volatile("cp.async.wait_group %0;" :: "n"(NSTG - 1) : "memory");
        __syncthreads();

        uint32_t* Bp = Bs + (kt % NSTG) * BSZW;
        COMPUTE_TILE64(A_s, Bp);
        __syncthreads();

        PREFETCH_B2(kt + NSTG);
    }

    // Epilogue: out shape (BATCH, INST, NVOCAB) fp32
#pragma unroll
    for (int s = 0; s < 4; s++) {
        int rowb = mt * 128 + wm + s * 16 + g;
#pragma unroll
        for (int q = 0; q < 8; q++) {
            int col = wn + q * 8 + 2 * tg;
            *reinterpret_cast<float2*>(out + ((size_t)rowb * INST + inst) * NVOCAB + col) =
                make_float2(c[s][q][0], c[s][q][1]);
            *reinterpret_cast<float2*>(out + ((size_t)(rowb + 8) * INST + inst) * NVOCAB + col) =
                make_float2(c[s][q][2], c[s][q][3]);
        }
    }
}

// ---------------------------------------------------------------------------
extern "C" void kernel_launch(void* const* d_in, const int* in_sizes, int n_in,
                              void* d_out, int out_size)
{
    const int*   a  = (const int*)d_in[0];
    const float* El = (const float*)d_in[1];
    const float* Er = (const float*)d_in[2];
    const float* W1 = (const float*)d_in[3];
    const float* W2 = (const float*)d_in[4];
    float* out = (float*)d_out;

    static int configured = 0;
    if (!configured) {
        cudaFuncSetAttribute(phase1_kernel,
                             cudaFuncAttributeMaxDynamicSharedMemorySize, GEMM_SMEM);
        cudaFuncSetAttribute(phase2_kernel,
                             cudaFuncAttributeMaxDynamicSharedMemorySize, GEMM_SMEM);
        configured = 1;
    }

    // W2 -> tf32 bit patterns
    w2t_kernel<<<(INST * HID * NVOCAB) / 1024, 256>>>(W2);

    dim3 g1(HID / 128, INST, 2);
    phase1_kernel<<<g1, 128, GEMM_SMEM>>>(El, Er, W1);

    dim3 g2(BATCH / 128, INST);
    phase2_kernel<<<g2, 128, GEMM_SMEM>>>(a, out);
}

// round 7
// speedup vs baseline: 1.0208x; 1.0208x over previous
#include <cuda_runtime.h>
#include <cuda_bf16.h>
#include <cstdint>
#include <math.h>

#define INST   64
#define NVOCAB 128
#define ED     256
#define HID    1024
#define BATCH  2048

// Precomputed HL[i] = E_l[i] @ W1[i], HR[i] = E_r[i] @ W1[i]  (fp32 scratch)
__device__ float g_HL[INST * NVOCAB * HID];
__device__ float g_HR[INST * NVOCAB * HID];
// W2 preconverted to tf32 bit patterns (filled by phase1 tail), [inst][k][n]
__device__ uint32_t g_W2t[INST * HID * NVOCAB];

__device__ __forceinline__ uint32_t f2tf(float f) {
    uint32_t u;
    asm("cvt.rna.tf32.f32 %0, %1;" : "=r"(u) : "f"(f));
    return u;
}
__device__ __forceinline__ void mma8(float* c, const uint32_t* a, const uint32_t* b) {
    asm volatile(
        "mma.sync.aligned.m16n8k8.row.col.f32.tf32.tf32.f32 "
        "{%0,%1,%2,%3}, {%4,%5,%6,%7}, {%8,%9}, {%0,%1,%2,%3};"
        : "+f"(c[0]), "+f"(c[1]), "+f"(c[2]), "+f"(c[3])
        : "r"(a[0]), "r"(a[1]), "r"(a[2]), "r"(a[3]), "r"(b[0]), "r"(b[1]));
}
__device__ __forceinline__ float gelu_exact(float x) {
    return 0.5f * x * (1.0f + erff(x * 0.7071067811865476f));
}
__device__ __forceinline__ uint32_t smem_u32(const void* p) {
    uint32_t a;
    asm("{ .reg .u64 t; cvta.to.shared.u64 t, %1; cvt.u32.u64 %0, t; }" : "=r"(a) : "l"(p));
    return a;
}

// Shared tile strides (words). Conflict-free fragment loads:
//   A bank = (4*row + k) % 32, B bank = (8*k + n) % 32
#define ASTR 36
#define BSTR 136
#define ASZW (128 * ASTR)     // 4608 words
#define BSZW (32 * BSTR)      // 4352 words
#define NKT  (HID / 32)       // 32 k-tiles in phase 2
#define NKT1 (ED / 32)        // 8 k-tiles in phase 1
#define NSTG1 3               // phase1 B pipeline depth
#define NSTG2 4               // phase2 B pipeline depth
#define P1_SMEM ((ASZW + NSTG1 * BSZW) * 4)           // 70656 B
#define P2_SMEM ((2 * ASZW + NSTG2 * BSZW) * 4)       // 106496 B

// 4-warp CTA, warp tile 64x64: s=4 m16-tiles, q=8 n8-tiles, 32 MMA/slice.
#define COMPUTE_TILE64(Ap, Bp)                                                  \
    _Pragma("unroll")                                                           \
    for (int ks = 0; ks < 4; ks++) {                                            \
        const int kk = ks * 8;                                                  \
        uint32_t af[4][4];                                                      \
        _Pragma("unroll")                                                       \
        for (int s = 0; s < 4; s++) {                                           \
            int r0 = wm + s * 16 + g;                                           \
            af[s][0] = (Ap)[r0 * ASTR + kk + tg];                               \
            af[s][1] = (Ap)[(r0 + 8) * ASTR + kk + tg];                         \
            af[s][2] = (Ap)[r0 * ASTR + kk + 4 + tg];                           \
            af[s][3] = (Ap)[(r0 + 8) * ASTR + kk + 4 + tg];                     \
        }                                                                       \
        uint32_t bf[8][2];                                                      \
        _Pragma("unroll")                                                       \
        for (int q = 0; q < 8; q++) {                                           \
            int nb = wn + q * 8 + g;                                            \
            bf[q][0] = (Bp)[(kk + tg) * BSTR + nb];                             \
            bf[q][1] = (Bp)[(kk + 4 + tg) * BSTR + nb];                         \
        }                                                                       \
        _Pragma("unroll")                                                       \
        for (int s = 0; s < 4; s++)                                             \
            _Pragma("unroll")                                                   \
            for (int q = 0; q < 8; q++)                                         \
                mma8(c[s][q], af[s], bf[q]);                                    \
    }

// ---------------------------------------------------------------------------
// Phase 1: HL/HR[i] = E[i] (128x256) @ W1[i] (256x1024)
// 4-warp 64x64 tiles, cp.async B (depth 3). grid (8, 64, 2), 128 threads.
// Tail: each CTA converts a slice of W2 -> tf32 into g_W2t.
// ---------------------------------------------------------------------------
__global__ __launch_bounds__(128) void phase1_kernel(
    const float* __restrict__ El, const float* __restrict__ Er,
    const float* __restrict__ W1, const float* __restrict__ W2)
{
    extern __shared__ uint32_t dsm[];
    uint32_t* A_s = dsm;
    uint32_t* Bs  = dsm + ASZW;
    const uint32_t bs_base = smem_u32(Bs);

    const int nt = blockIdx.x, inst = blockIdx.y, side = blockIdx.z;
    const float* E   = (side ? Er : El) + inst * NVOCAB * ED;
    float*       Hst = (side ? g_HR : g_HL) + inst * NVOCAB * HID + nt * 128;
    const float* W   = W1 + inst * ED * HID + nt * 128;

    const int t    = threadIdx.x;
    const int lane = t & 31, w = t >> 5;
    const int wm = (w & 1) * 64, wn = (w >> 1) * 64;
    const int g = lane >> 2, tg = lane & 3;
    const int r0a = t >> 2, c8 = (t & 3) * 8;

    float c[4][8][4];
#pragma unroll
    for (int s = 0; s < 4; s++)
#pragma unroll
        for (int q = 0; q < 8; q++)
#pragma unroll
            for (int v = 0; v < 4; v++) c[s][q][v] = 0.f;

#define PREFETCH_B1(KT) do {                                                    \
        if ((KT) < NKT1) {                                                      \
            const uint32_t bb = bs_base + (uint32_t)((((KT) % NSTG1)) * (BSZW * 4)); \
            const float* srcb = W + (size_t)(KT) * 32 * HID;                    \
            _Pragma("unroll")                                                   \
            for (int j = 0; j < 8; j++) {                                       \
                int cc = t + 128 * j;                                           \
                int k = cc >> 5, nc = (cc & 31) * 4;                            \
                uint32_t dst = bb + (uint32_t)(k * BSTR + nc) * 4;              \
                const float* src = srcb + (size_t)k * HID + nc;                 \
                asm volatile("cp.async.cg.shared.global [%0], [%1], 16;"        \
                             :: "r"(dst), "l"(src) : "memory");                 \
            }                                                                   \
        }                                                                       \
        asm volatile("cp.async.commit_group;" ::: "memory");                    \
    } while (0)

    PREFETCH_B1(0); PREFETCH_B1(1); PREFETCH_B1(2);

#pragma unroll 1
    for (int kt = 0; kt < NKT1; kt++) {
        const int k0 = kt * 32;
        // Produce A tile: tf32 convert of E rows
#pragma unroll
        for (int j = 0; j < 4; j++) {
            int row = r0a + 32 * j;
            float4 v0 = *reinterpret_cast<const float4*>(E + row * ED + k0 + c8);
            float4 v1 = *reinterpret_cast<const float4*>(E + row * ED + k0 + c8 + 4);
            *reinterpret_cast<uint4*>(&A_s[row * ASTR + c8]) =
                make_uint4(f2tf(v0.x), f2tf(v0.y), f2tf(v0.z), f2tf(v0.w));
            *reinterpret_cast<uint4*>(&A_s[row * ASTR + c8 + 4]) =
                make_uint4(f2tf(v1.x), f2tf(v1.y), f2tf(v1.z), f2tf(v1.w));
        }
        asm volatile("cp.async.wait_group %0;" :: "n"(NSTG1 - 1) : "memory");
        __syncthreads();

        // Convert B tile fp32 -> tf32 in smem
        uint32_t* Bp = Bs + (kt % NSTG1) * BSZW;
#pragma unroll
        for (int j = 0; j < 8; j++) {
            int cc = t + 128 * j;
            int k = cc >> 5, nc = (cc & 31) * 4;
            uint4* p = reinterpret_cast<uint4*>(&Bp[k * BSTR + nc]);
            uint4 u = *p;
            u.x = f2tf(__uint_as_float(u.x));
            u.y = f2tf(__uint_as_float(u.y));
            u.z = f2tf(__uint_as_float(u.z));
            u.w = f2tf(__uint_as_float(u.w));
            *p = u;
        }
        __syncthreads();
        COMPUTE_TILE64(A_s, Bp);
        __syncthreads();
        PREFETCH_B1(kt + NSTG1);
    }

#pragma unroll
    for (int s = 0; s < 4; s++) {
        int row = wm + s * 16 + g;
#pragma unroll
        for (int q = 0; q < 8; q++) {
            int col = wn + q * 8 + 2 * tg;
            *reinterpret_cast<float2*>(Hst + row * HID + col) =
                make_float2(c[s][q][0], c[s][q][1]);
            *reinterpret_cast<float2*>(Hst + (row + 8) * HID + col) =
                make_float2(c[s][q][2], c[s][q][3]);
        }
    }

    // Tail: W2 -> tf32 (whole grid covers all of W2, coalesced, 16 uint4/thread)
    {
        size_t gtid = (((size_t)blockIdx.z * INST + blockIdx.y) * (HID / 128)
                       + blockIdx.x) * 128 + t;
        const size_t nthreads = (size_t)2 * INST * (HID / 128) * 128;  // 131072
#pragma unroll
        for (int j = 0; j < 16; j++) {
            size_t idx = (j * nthreads + gtid) * 4;
            float4 v = *reinterpret_cast<const float4*>(W2 + idx);
            *reinterpret_cast<uint4*>(g_W2t + idx) =
                make_uint4(f2tf(v.x), f2tf(v.y), f2tf(v.z), f2tf(v.w));
        }
    }
}

// ---------------------------------------------------------------------------
// Phase 2: out[b,i,:] = gelu(HL[i,a1[b],:] + HR[i,a2[b],:]) @ W2[i]
// Produce-ahead pipeline: A(kt+2) LDG issues before compute(kt); A(kt+1)
// gelu+STS into double-buffered A tile after compute(kt). One sync/iter.
// B tf32 via cp.async, 4 stages. grid (16, 64), 128 threads.
// ---------------------------------------------------------------------------
__global__ __launch_bounds__(128) void phase2_kernel(
    const int* __restrict__ a, float* __restrict__ out)
{
    extern __shared__ uint32_t dsm[];
    uint32_t* Ab[2] = { dsm, dsm + ASZW };
    uint32_t* Bs  = dsm + 2 * ASZW;
    const uint32_t bs_base = smem_u32(Bs);

    const int mt = blockIdx.x, inst = blockIdx.y;
    const uint32_t* Wt = g_W2t + (size_t)inst * HID * NVOCAB;

    const int t    = threadIdx.x;
    const int lane = t & 31, w = t >> 5;
    const int wm = (w & 1) * 64, wn = (w >> 1) * 64;
    const int g = lane >> 2, tg = lane & 3;
    const int r0a = t >> 2, c8 = (t & 3) * 8;

    // Hoist gather offsets (u32 byte offsets into g_HL/g_HR)
    uint32_t offL[4], offR[4];
#pragma unroll
    for (int j = 0; j < 4; j++) {
        int row = r0a + 32 * j;
        int b = mt * 128 + row;
        int i1 = a[2 * b], i2 = a[2 * b + 1];
        offL[j] = (uint32_t)(inst * NVOCAB + i1) * (HID * 4);
        offR[j] = (uint32_t)(inst * NVOCAB + i2) * (HID * 4);
    }
    const char* baseL = (const char*)g_HL;
    const char* baseR = (const char*)g_HR;

    float c[4][8][4];
#pragma unroll
    for (int s = 0; s < 4; s++)
#pragma unroll
        for (int q = 0; q < 8; q++)
#pragma unroll
            for (int v = 0; v < 4; v++) c[s][q][v] = 0.f;

    // Register-staged A sums (4 rows x 8 floats) — 128 threads => no reg cap.
    float4 s0[4], s1[4];

#define LDGSUM(KT) do {                                                         \
        const uint32_t kb = (uint32_t)((KT) * 32 + c8) * 4;                     \
        _Pragma("unroll")                                                       \
        for (int j = 0; j < 4; j++) {                                           \
            float4 l0 = *reinterpret_cast<const float4*>(baseL + offL[j] + kb); \
            float4 l1 = *reinterpret_cast<const float4*>(baseL + offL[j] + kb + 16); \
            float4 q0 = *reinterpret_cast<const float4*>(baseR + offR[j] + kb); \
            float4 q1 = *reinterpret_cast<const float4*>(baseR + offR[j] + kb + 16); \
            s0[j] = make_float4(l0.x + q0.x, l0.y + q0.y, l0.z + q0.z, l0.w + q0.w); \
            s1[j] = make_float4(l1.x + q1.x, l1.y + q1.y, l1.z + q1.z, l1.w + q1.w); \
        }                                                                       \
    } while (0)

#define GELUSTS(Ap) do {                                                        \
        _Pragma("unroll")                                                       \
        for (int j = 0; j < 4; j++) {                                           \
            int row = r0a + 32 * j;                                             \
            uint4 u0, u1;                                                       \
            u0.x = f2tf(gelu_exact(s0[j].x));                                   \
            u0.y = f2tf(gelu_exact(s0[j].y));                                   \
            u0.z = f2tf(gelu_exact(s0[j].z));                                   \
            u0.w = f2tf(gelu_exact(s0[j].w));                                   \
            u1.x = f2tf(gelu_exact(s1[j].x));                                   \
            u1.y = f2tf(gelu_exact(s1[j].y));                                   \
            u1.z = f2tf(gelu_exact(s1[j].z));                                   \
            u1.w = f2tf(gelu_exact(s1[j].w));                                   \
            *reinterpret_cast<uint4*>(&(Ap)[row * ASTR + c8]) = u0;             \
            *reinterpret_cast<uint4*>(&(Ap)[row * ASTR + c8 + 4]) = u1;         \
        }                                                                       \
    } while (0)

#define PREFETCH_B2(KT) do {                                                    \
        if ((KT) < NKT) {                                                       \
            const uint32_t bb = bs_base + (uint32_t)((((KT) % NSTG2)) * (BSZW * 4)); \
            const uint32_t* srcb = Wt + (size_t)(KT) * 32 * NVOCAB;             \
            _Pragma("unroll")                                                   \
            for (int j = 0; j < 8; j++) {                                       \
                int cc = t + 128 * j;                                           \
                int k = cc >> 5, nc = (cc & 31) * 4;                            \
                uint32_t dst = bb + (uint32_t)(k * BSTR + nc) * 4;              \
                const uint32_t* src = srcb + k * NVOCAB + nc;                   \
                asm volatile("cp.async.cg.shared.global [%0], [%1], 16;"        \
                             :: "r"(dst), "l"(src) : "memory");                 \
            }                                                                   \
        }                                                                       \
        asm volatile("cp.async.commit_group;" ::: "memory");                    \
    } while (0)

    // Prologue: A(0) into buf0, A(1) staged in regs; B stages 0..2 in flight.
    LDGSUM(0);
    GELUSTS(Ab[0]);
    LDGSUM(1);
    PREFETCH_B2(0); PREFETCH_B2(1); PREFETCH_B2(2);

#pragma unroll 1
    for (int kt = 0; kt < NKT; kt++) {
        // B(kt) copies (3 groups pending -> wait<=2 completes B(kt))
        asm volatile("cp.async.wait_group 2;" ::: "memory");
        __syncthreads();   // B(kt) visible to all; compute(kt-1) & A stores closed

        PREFETCH_B2(kt + 3);   // slot (kt+3)%4 == (kt-1)%4: its readers finished

        COMPUTE_TILE64(Ab[kt & 1], Bs + (kt & 3) * BSZW);

        if (kt + 1 < NKT) GELUSTS(Ab[(kt + 1) & 1]);  // consumes regs from last iter
        if (kt + 2 < NKT) LDGSUM(kt + 2);             // issue early; hides under next compute
    }

    // Epilogue: out shape (BATCH, INST, NVOCAB) fp32
#pragma unroll
    for (int s = 0; s < 4; s++) {
        int rowb = mt * 128 + wm + s * 16 + g;
#pragma unroll
        for (int q = 0; q < 8; q++) {
            int col = wn + q * 8 + 2 * tg;
            *reinterpret_cast<float2*>(out + ((size_t)rowb * INST + inst) * NVOCAB + col) =
                make_float2(c[s][q][0], c[s][q][1]);
            *reinterpret_cast<float2*>(out + ((size_t)(rowb + 8) * INST + inst) * NVOCAB + col) =
                make_float2(c[s][q][2], c[s][q][3]);
        }
    }
}

// ---------------------------------------------------------------------------
extern "C" void kernel_launch(void* const* d_in, const int* in_sizes, int n_in,
                              void* d_out, int out_size)
{
    const int*   a  = (const int*)d_in[0];
    const float* El = (const float*)d_in[1];
    const float* Er = (const float*)d_in[2];
    const float* W1 = (const float*)d_in[3];
    const float* W2 = (const float*)d_in[4];
    float* out = (float*)d_out;

    static int configured = 0;
    if (!configured) {
        cudaFuncSetAttribute(phase1_kernel,
                             cudaFuncAttributeMaxDynamicSharedMemorySize, P1_SMEM);
        cudaFuncSetAttribute(phase2_kernel,
                             cudaFuncAttributeMaxDynamicSharedMemorySize, P2_SMEM);
        configured = 1;
    }

    dim3 g1(HID / 128, INST, 2);
    phase1_kernel<<<g1, 128, P1_SMEM>>>(El, Er, W1, W2);

    dim3 g2(BATCH / 128, INST);
    phase2_kernel<<<g2, 128, P2_SMEM>>>(a, out);
}

// round 8
// speedup vs baseline: 1.0547x; 1.0332x over previous
#include <cuda_runtime.h>
#include <cuda_bf16.h>
#include <cstdint>
#include <math.h>

#define INST   64
#define NVOCAB 128
#define ED     256
#define HID    1024
#define BATCH  2048

// Precomputed HL[i] = E_l[i] @ W1[i], HR[i] = E_r[i] @ W1[i]  (fp32 scratch)
__device__ float g_HL[INST * NVOCAB * HID];
__device__ float g_HR[INST * NVOCAB * HID];
// W2 preconverted to tf32 bit patterns (filled by phase1 tail), [inst][k][n]
__device__ uint32_t g_W2t[INST * HID * NVOCAB];

__device__ __forceinline__ uint32_t f2tf(float f) {
    uint32_t u;
    asm("cvt.rna.tf32.f32 %0, %1;" : "=r"(u) : "f"(f));
    return u;
}
__device__ __forceinline__ void mma8(float* c, const uint32_t* a, const uint32_t* b) {
    asm volatile(
        "mma.sync.aligned.m16n8k8.row.col.f32.tf32.tf32.f32 "
        "{%0,%1,%2,%3}, {%4,%5,%6,%7}, {%8,%9}, {%0,%1,%2,%3};"
        : "+f"(c[0]), "+f"(c[1]), "+f"(c[2]), "+f"(c[3])
        : "r"(a[0]), "r"(a[1]), "r"(a[2]), "r"(a[3]), "r"(b[0]), "r"(b[1]));
}
__device__ __forceinline__ float gelu_exact(float x) {
    return 0.5f * x * (1.0f + erff(x * 0.7071067811865476f));
}
__device__ __forceinline__ uint32_t smem_u32(const void* p) {
    uint32_t a;
    asm("{ .reg .u64 t; cvta.to.shared.u64 t, %1; cvt.u32.u64 %0, t; }" : "=r"(a) : "l"(p));
    return a;
}

// Shared tile strides (words). Conflict-free fragment loads:
//   A bank = (4*row + k) % 32, B bank = (8*k + n) % 32
#define ASTR 36
#define BSTR 136
#define ASZW (128 * ASTR)     // 4608 words
#define BSZW (32 * BSTR)      // 4352 words
#define NKT  (HID / 32)       // 32 k-tiles in phase 2
#define NKT1 (ED / 32)        // 8 k-tiles in phase 1
#define NSTG1 3               // phase1 B pipeline depth
#define NSTG2 4               // phase2 B pipeline depth
#define P1_SMEM ((ASZW + NSTG1 * BSZW) * 4)           // 70656 B
#define P2_SMEM ((2 * ASZW + NSTG2 * BSZW) * 4)       // 106496 B

// 8-warp CTA, warp tile 64x32: wm=(w&1)*64, wn=(w>>1)*32.
// s=4 m16-tiles, q=4 n8-tiles, 16 MMA/slice, accum 64 regs/thread.
#define COMPUTE_TILE6432(Ap, Bp)                                                \
    _Pragma("unroll")                                                           \
    for (int ks = 0; ks < 4; ks++) {                                            \
        const int kk = ks * 8;                                                  \
        uint32_t af[4][4];                                                      \
        _Pragma("unroll")                                                       \
        for (int s = 0; s < 4; s++) {                                           \
            int r0 = wm + s * 16 + g;                                           \
            af[s][0] = (Ap)[r0 * ASTR + kk + tg];                               \
            af[s][1] = (Ap)[(r0 + 8) * ASTR + kk + tg];                         \
            af[s][2] = (Ap)[r0 * ASTR + kk + 4 + tg];                           \
            af[s][3] = (Ap)[(r0 + 8) * ASTR + kk + 4 + tg];                     \
        }                                                                       \
        uint32_t bf[4][2];                                                      \
        _Pragma("unroll")                                                       \
        for (int q = 0; q < 4; q++) {                                           \
            int nb = wn + q * 8 + g;                                            \
            bf[q][0] = (Bp)[(kk + tg) * BSTR + nb];                             \
            bf[q][1] = (Bp)[(kk + 4 + tg) * BSTR + nb];                         \
        }                                                                       \
        _Pragma("unroll")                                                       \
        for (int s = 0; s < 4; s++)                                             \
            _Pragma("unroll")                                                   \
            for (int q = 0; q < 4; q++)                                         \
                mma8(c[s][q], af[s], bf[q]);                                    \
    }

// ---------------------------------------------------------------------------
// Phase 1: HL/HR[i] = E[i] (128x256) @ W1[i] (256x1024)
// 8-warp 64x32 tiles, cp.async B depth 3. grid (8, 64, 2), 256 threads.
// Tail: grid-wide W2 -> tf32 conversion into g_W2t.
// ---------------------------------------------------------------------------
__global__ __launch_bounds__(256, 2) void phase1_kernel(
    const float* __restrict__ El, const float* __restrict__ Er,
    const float* __restrict__ W1, const float* __restrict__ W2)
{
    extern __shared__ uint32_t dsm[];
    uint32_t* A_s = dsm;
    uint32_t* Bs  = dsm + ASZW;
    const uint32_t bs_base = smem_u32(Bs);

    const int nt = blockIdx.x, inst = blockIdx.y, side = blockIdx.z;
    const float* E   = (side ? Er : El) + inst * NVOCAB * ED;
    float*       Hst = (side ? g_HR : g_HL) + inst * NVOCAB * HID + nt * 128;
    const float* W   = W1 + inst * ED * HID + nt * 128;

    const int t    = threadIdx.x;
    const int lane = t & 31, w = t >> 5;
    const int wm = (w & 1) * 64, wn = (w >> 1) * 32;
    const int g = lane >> 2, tg = lane & 3;
    // A-producer: rows r0a, r0a+64; col group c8 = (t&3)*8
    const int r0a = t >> 2, c8 = (t & 3) * 8;

    float c[4][4][4];
#pragma unroll
    for (int s = 0; s < 4; s++)
#pragma unroll
        for (int q = 0; q < 4; q++)
#pragma unroll
            for (int v = 0; v < 4; v++) c[s][q][v] = 0.f;

#define PREFETCH_B1(KT) do {                                                    \
        if ((KT) < NKT1) {                                                      \
            const uint32_t bb = bs_base + (uint32_t)((((KT) % NSTG1)) * (BSZW * 4)); \
            const float* srcb = W + (size_t)(KT) * 32 * HID;                    \
            _Pragma("unroll")                                                   \
            for (int j = 0; j < 4; j++) {                                       \
                int cc = t + 256 * j;                                           \
                int k = cc >> 5, nc = (cc & 31) * 4;                            \
                uint32_t dst = bb + (uint32_t)(k * BSTR + nc) * 4;              \
                const float* src = srcb + (size_t)k * HID + nc;                 \
                asm volatile("cp.async.cg.shared.global [%0], [%1], 16;"        \
                             :: "r"(dst), "l"(src) : "memory");                 \
            }                                                                   \
        }                                                                       \
        asm volatile("cp.async.commit_group;" ::: "memory");                    \
    } while (0)

    PREFETCH_B1(0); PREFETCH_B1(1); PREFETCH_B1(2);

#pragma unroll 1
    for (int kt = 0; kt < NKT1; kt++) {
        const int k0 = kt * 32;
        // Produce A tile: tf32 convert of E rows (2 rows/thread)
#pragma unroll
        for (int j = 0; j < 2; j++) {
            int row = r0a + 64 * j;
            float4 v0 = *reinterpret_cast<const float4*>(E + row * ED + k0 + c8);
            float4 v1 = *reinterpret_cast<const float4*>(E + row * ED + k0 + c8 + 4);
            *reinterpret_cast<uint4*>(&A_s[row * ASTR + c8]) =
                make_uint4(f2tf(v0.x), f2tf(v0.y), f2tf(v0.z), f2tf(v0.w));
            *reinterpret_cast<uint4*>(&A_s[row * ASTR + c8 + 4]) =
                make_uint4(f2tf(v1.x), f2tf(v1.y), f2tf(v1.z), f2tf(v1.w));
        }
        asm volatile("cp.async.wait_group %0;" :: "n"(NSTG1 - 1) : "memory");
        __syncthreads();

        // Convert B tile fp32 -> tf32 in smem
        uint32_t* Bp = Bs + (kt % NSTG1) * BSZW;
#pragma unroll
        for (int j = 0; j < 4; j++) {
            int cc = t + 256 * j;
            int k = cc >> 5, nc = (cc & 31) * 4;
            uint4* p = reinterpret_cast<uint4*>(&Bp[k * BSTR + nc]);
            uint4 u = *p;
            u.x = f2tf(__uint_as_float(u.x));
            u.y = f2tf(__uint_as_float(u.y));
            u.z = f2tf(__uint_as_float(u.z));
            u.w = f2tf(__uint_as_float(u.w));
            *p = u;
        }
        __syncthreads();
        COMPUTE_TILE6432(A_s, Bp);
        __syncthreads();
        PREFETCH_B1(kt + NSTG1);
    }

#pragma unroll
    for (int s = 0; s < 4; s++) {
        int row = wm + s * 16 + g;
#pragma unroll
        for (int q = 0; q < 4; q++) {
            int col = wn + q * 8 + 2 * tg;
            *reinterpret_cast<float2*>(Hst + row * HID + col) =
                make_float2(c[s][q][0], c[s][q][1]);
            *reinterpret_cast<float2*>(Hst + (row + 8) * HID + col) =
                make_float2(c[s][q][2], c[s][q][3]);
        }
    }

    // Tail: W2 -> tf32 (whole grid, coalesced, 8 uint4/thread)
    {
        size_t gtid = (((size_t)blockIdx.z * INST + blockIdx.y) * (HID / 128)
                       + blockIdx.x) * 256 + t;
        const size_t nthreads = (size_t)2 * INST * (HID / 128) * 256;  // 262144
#pragma unroll
        for (int j = 0; j < 8; j++) {
            size_t idx = (j * nthreads + gtid) * 4;
            float4 v = *reinterpret_cast<const float4*>(W2 + idx);
            *reinterpret_cast<uint4*>(g_W2t + idx) =
                make_uint4(f2tf(v.x), f2tf(v.y), f2tf(v.z), f2tf(v.w));
        }
    }
}

// ---------------------------------------------------------------------------
// Phase 2: out[b,i,:] = gelu(HL[i,a1[b],:] + HR[i,a2[b],:]) @ W2[i]
// 8-warp 64x32 tiles, produce-ahead pipeline, one sync/iter, B depth 4.
// grid (16, 64), 256 threads, 2 CTAs/SM -> 16 warps/SM.
// ---------------------------------------------------------------------------
__global__ __launch_bounds__(256, 2) void phase2_kernel(
    const int* __restrict__ a, float* __restrict__ out)
{
    extern __shared__ uint32_t dsm[];
    uint32_t* Ab[2] = { dsm, dsm + ASZW };
    uint32_t* Bs  = dsm + 2 * ASZW;
    const uint32_t bs_base = smem_u32(Bs);

    const int mt = blockIdx.x, inst = blockIdx.y;
    const uint32_t* Wt = g_W2t + (size_t)inst * HID * NVOCAB;

    const int t    = threadIdx.x;
    const int lane = t & 31, w = t >> 5;
    const int wm = (w & 1) * 64, wn = (w >> 1) * 32;
    const int g = lane >> 2, tg = lane & 3;
    const int r0a = t >> 2, c8 = (t & 3) * 8;

    // Hoist gather offsets: 2 rows/thread (r0a, r0a+64)
    uint32_t offL[2], offR[2];
#pragma unroll
    for (int j = 0; j < 2; j++) {
        int row = r0a + 64 * j;
        int b = mt * 128 + row;
        int i1 = a[2 * b], i2 = a[2 * b + 1];
        offL[j] = (uint32_t)(inst * NVOCAB + i1) * (HID * 4);
        offR[j] = (uint32_t)(inst * NVOCAB + i2) * (HID * 4);
    }
    const char* baseL = (const char*)g_HL;
    const char* baseR = (const char*)g_HR;

    float c[4][4][4];
#pragma unroll
    for (int s = 0; s < 4; s++)
#pragma unroll
        for (int q = 0; q < 4; q++)
#pragma unroll
            for (int v = 0; v < 4; v++) c[s][q][v] = 0.f;

    // Staged A sums: 2 rows x 8 floats = 16 regs
    float4 s0[2], s1[2];

#define LDGSUM(KT) do {                                                         \
        const uint32_t kb = (uint32_t)((KT) * 32 + c8) * 4;                     \
        _Pragma("unroll")                                                       \
        for (int j = 0; j < 2; j++) {                                           \
            float4 l0 = *reinterpret_cast<const float4*>(baseL + offL[j] + kb); \
            float4 l1 = *reinterpret_cast<const float4*>(baseL + offL[j] + kb + 16); \
            float4 q0 = *reinterpret_cast<const float4*>(baseR + offR[j] + kb); \
            float4 q1 = *reinterpret_cast<const float4*>(baseR + offR[j] + kb + 16); \
            s0[j] = make_float4(l0.x + q0.x, l0.y + q0.y, l0.z + q0.z, l0.w + q0.w); \
            s1[j] = make_float4(l1.x + q1.x, l1.y + q1.y, l1.z + q1.z, l1.w + q1.w); \
        }                                                                       \
    } while (0)

#define GELUSTS(Ap) do {                                                        \
        _Pragma("unroll")                                                       \
        for (int j = 0; j < 2; j++) {                                           \
            int row = r0a + 64 * j;                                             \
            uint4 u0, u1;                                                       \
            u0.x = f2tf(gelu_exact(s0[j].x));                                   \
            u0.y = f2tf(gelu_exact(s0[j].y));                                   \
            u0.z = f2tf(gelu_exact(s0[j].z));                                   \
            u0.w = f2tf(gelu_exact(s0[j].w));                                   \
            u1.x = f2tf(gelu_exact(s1[j].x));                                   \
            u1.y = f2tf(gelu_exact(s1[j].y));                                   \
            u1.z = f2tf(gelu_exact(s1[j].z));                                   \
            u1.w = f2tf(gelu_exact(s1[j].w));                                   \
            *reinterpret_cast<uint4*>(&(Ap)[row * ASTR + c8]) = u0;             \
            *reinterpret_cast<uint4*>(&(Ap)[row * ASTR + c8 + 4]) = u1;         \
        }                                                                       \
    } while (0)

#define PREFETCH_B2(KT) do {                                                    \
        if ((KT) < NKT) {                                                       \
            const uint32_t bb = bs_base + (uint32_t)((((KT) % NSTG2)) * (BSZW * 4)); \
            const uint32_t* srcb = Wt + (size_t)(KT) * 32 * NVOCAB;             \
            _Pragma("unroll")                                                   \
            for (int j = 0; j < 4; j++) {                                       \
                int cc = t + 256 * j;                                           \
                int k = cc >> 5, nc = (cc & 31) * 4;                            \
                uint32_t dst = bb + (uint32_t)(k * BSTR + nc) * 4;              \
                const uint32_t* src = srcb + k * NVOCAB + nc;                   \
                asm volatile("cp.async.cg.shared.global [%0], [%1], 16;"        \
                             :: "r"(dst), "l"(src) : "memory");                 \
            }                                                                   \
        }                                                                       \
        asm volatile("cp.async.commit_group;" ::: "memory");                    \
    } while (0)

    // Prologue: A(0) in buf0; A(1) staged; B stages 0..2 in flight.
    LDGSUM(0);
    GELUSTS(Ab[0]);
    LDGSUM(1);
    PREFETCH_B2(0); PREFETCH_B2(1); PREFETCH_B2(2);

#pragma unroll 1
    for (int kt = 0; kt < NKT; kt++) {
        asm volatile("cp.async.wait_group 2;" ::: "memory");
        __syncthreads();   // B(kt) + A stores visible; compute(kt-1) closed

        PREFETCH_B2(kt + 3);   // reuses slot of B(kt-1), readers done

        COMPUTE_TILE6432(Ab[kt & 1], Bs + (kt & 3) * BSZW);

        if (kt + 1 < NKT) GELUSTS(Ab[(kt + 1) & 1]);
        if (kt + 2 < NKT) LDGSUM(kt + 2);
    }

    // Epilogue: out shape (BATCH, INST, NVOCAB) fp32
#pragma unroll
    for (int s = 0; s < 4; s++) {
        int rowb = mt * 128 + wm + s * 16 + g;
#pragma unroll
        for (int q = 0; q < 4; q++) {
            int col = wn + q * 8 + 2 * tg;
            *reinterpret_cast<float2*>(out + ((size_t)rowb * INST + inst) * NVOCAB + col) =
                make_float2(c[s][q][0], c[s][q][1]);
            *reinterpret_cast<float2*>(out + ((size_t)(rowb + 8) * INST + inst) * NVOCAB + col) =
                make_float2(c[s][q][2], c[s][q][3]);
        }
    }
}

// ---------------------------------------------------------------------------
extern "C" void kernel_launch(void* const* d_in, const int* in_sizes, int n_in,
                              void* d_out, int out_size)
{
    const int*   a  = (const int*)d_in[0];
    const float* El = (const float*)d_in[1];
    const float* Er = (const float*)d_in[2];
    const float* W1 = (const float*)d_in[3];
    const float* W2 = (const float*)d_in[4];
    float* out = (float*)d_out;

    static int configured = 0;
    if (!configured) {
        cudaFuncSetAttribute(phase1_kernel,
                             cudaFuncAttributeMaxDynamicSharedMemorySize, P1_SMEM);
        cudaFuncSetAttribute(phase2_kernel,
                             cudaFuncAttributeMaxDynamicSharedMemorySize, P2_SMEM);
        configured = 1;
    }

    dim3 g1(HID / 128, INST, 2);
    phase1_kernel<<<g1, 256, P1_SMEM>>>(El, Er, W1, W2);

    dim3 g2(BATCH / 128, INST);
    phase2_kernel<<<g2, 256, P2_SMEM>>>(a, out);
}